// round 7
// baseline (speedup 1.0000x reference)
#include <cuda_runtime.h>
#include <cuda_fp16.h>
#include <cstdint>
#include <cstddef>

// ============================================================================
// TT linear layer, fused Kronecker-sandwich, register-resident Z, software-
// pipelined across r2:
//   Y_b = sum_{r2=0..15}  L2_r2 (64x64) . X_b (64x64) . R2_r2^T (64x64)
// CTA = 4 samples, 256 threads = 8 warps. Warp w: sample bb=w&3, n34-half w>>2.
// Body i interleaves GEMM2(i-1) (accY += pack(z) . L2) with GEMM1(i)
// (z rebuilt IN PLACE from R2 . X^T via fresh-write MMA at ks=0), per-p-block,
// so independent GEMM2 MMAs fill GEMM1's dependency/LDSM bubbles.
// Factor ring slot j = {R2(j), L2(j-1)}  ->  body i reads exactly slot i.
// 8-slot ring, prefetch distance 4, barrier every 4 bodies (round-6 scheme).
// ============================================================================

__device__ __forceinline__ uint32_t smem_u32(const void* p) {
    uint32_t a;
    asm("{ .reg .u64 t; cvta.to.shared.u64 t, %1; cvt.u32.u64 %0, t; }" : "=r"(a) : "l"(p));
    return a;
}
__device__ __forceinline__ void cpa16(uint32_t d, const void* s) {
    asm volatile("cp.async.cg.shared.global [%0], [%1], 16;" :: "r"(d), "l"(s));
}
#define CP_COMMIT() asm volatile("cp.async.commit_group;" ::: "memory")
#define CP_WAIT0()  asm volatile("cp.async.wait_group 0;" ::: "memory")

// D += A*B (accumulate)
#define MMA16(d, a0, a1, a2, a3, b0, b1) asm volatile( \
    "mma.sync.aligned.m16n8k16.row.col.f32.f16.f16.f32 " \
    "{%0,%1,%2,%3},{%4,%5,%6,%7},{%8,%9},{%0,%1,%2,%3};" \
    : "+f"((d)[0]), "+f"((d)[1]), "+f"((d)[2]), "+f"((d)[3]) \
    : "r"(a0), "r"(a1), "r"(a2), "r"(a3), "r"(b0), "r"(b1))

// D = A*B (fresh write, C = 0 -> RZ)
#define MMA16Z(d, a0, a1, a2, a3, b0, b1) asm volatile( \
    "mma.sync.aligned.m16n8k16.row.col.f32.f16.f16.f32 " \
    "{%0,%1,%2,%3},{%4,%5,%6,%7},{%8,%9},{%10,%10,%10,%10};" \
    : "=f"((d)[0]), "=f"((d)[1]), "=f"((d)[2]), "=f"((d)[3]) \
    : "r"(a0), "r"(a1), "r"(a2), "r"(a3), "r"(b0), "r"(b1), "f"(0.f))

#define LDSM4(r0, r1, r2_, r3, addr) asm volatile( \
    "ldmatrix.sync.aligned.m8n8.x4.shared.b16 {%0,%1,%2,%3}, [%4];" \
    : "=r"(r0), "=r"(r1), "=r"(r2_), "=r"(r3) : "r"(addr))

__device__ __forceinline__ uint32_t packh2(float lo, float hi) {
    uint32_t r;
    asm("cvt.rn.f16x2.f32 %0, %2, %1;" : "=r"(r) : "f"(lo), "f"(hi));
    return r;
}

// ---------------- layout constants (fp16 element units) --------------------
static constexpr int LDX = 72;    // X   [256][64]   (144B rows, LDSM-safe)
static constexpr int LDR = 72;    // R/L [64][64]
static constexpr int OFF_X = 0;                          // 256*72 = 18432
static constexpr int OFF_F = 18432;
static constexpr int FBUF  = 2 * 64 * LDR;               // 9216 halves {R | L}
static constexpr int NSLOT = 8;                          // factor ring depth
static constexpr int SMEM_HALFS = OFF_F + NSLOT * FBUF;  // 92160
static constexpr uint32_t SMEM_BYTES = SMEM_HALFS * 2;   // 184320

// ---------------- device-side factor slices --------------------------------
__device__ __half g_R2h[16 * 64 * 64];   // [r2][n34][m34]
__device__ __half g_L2h[16 * 64 * 64];   // [r2][n12][m12]

// ---------------- prep: both factor contractions in one kernel -------------
__global__ void k_prep(const float* __restrict__ c0, const float* __restrict__ c1,
                       const float* __restrict__ c2, const float* __restrict__ c3) {
    int t = blockIdx.x * 256 + threadIdx.x;      // 0..131071
    if (t < 65536) {
        int m34 = t & 63, n34 = (t >> 6) & 63, r2 = t >> 12;
        int m3 = m34 >> 3, m4 = m34 & 7, n3 = n34 >> 3, n4 = n34 & 7;
        float s = 0.f;
#pragma unroll
        for (int r3 = 0; r3 < 16; r3++)
            s += c2[((r2 * 8 + n3) * 8 + m3) * 16 + r3] * c3[(r3 * 8 + n4) * 8 + m4];
        g_R2h[t] = __float2half_rn(s);
    } else {
        int u = t - 65536;
        int m12 = u & 63, n12 = (u >> 6) & 63, r2 = u >> 12;
        int m1 = m12 >> 3, m2 = m12 & 7, n1 = n12 >> 3, n2 = n12 & 7;
        float s = 0.f;
#pragma unroll
        for (int r1 = 0; r1 < 16; r1++)
            s += c0[(n1 * 8 + m1) * 16 + r1] * c1[((r1 * 8 + n2) * 8 + m2) * 16 + r2];
        g_L2h[u] = __float2half_rn(s);
    }
}

// ---------------- prefetch slot j = { R2(j), L2(j-1) } ----------------------
__device__ __forceinline__ void prefetch_slot(uint32_t sb, int tid, int j) {
    const uint32_t f0 = sb + (uint32_t)(OFF_F + (j & (NSLOT - 1)) * FBUF) * 2u;
    const int jr = (j < 15) ? j : 15;        // R(16) never read; clamp
    const int jl = (j > 0) ? (j - 1) : 0;    // L(-1) never read; clamp
    const __half* gR = g_R2h + jr * 4096;
    const __half* gL = g_L2h + jl * 4096;
#pragma unroll
    for (int k = 0; k < 2; k++) {
        int i = tid + k * 256;            // 0..511 16B chunks
        int row = i >> 3, c = i & 7;
        uint32_t d = (uint32_t)(row * LDR + c * 8) * 2u;
        cpa16(f0 + d, gR + row * 64 + c * 8);
        cpa16(f0 + (uint32_t)(64 * LDR) * 2u + d, gL + row * 64 + c * 8);
    }
    CP_COMMIT();
}

// ---------------- pipelined body: GEMM2(i-1) interleaved with GEMM1(i) ------
template <bool G2, bool G1>
__device__ __forceinline__ void body(
    uint32_t sb, uint32_t slotB,
    float (&z)[2][8][4], float (&accY)[2][8][4],
    int half34, int bb, int aRow, int aCol, int bRow, int bCol)
{
    const uint32_t fR = slotB;                              // R2(i)
    const uint32_t fL = slotB + (uint32_t)(64 * LDR) * 2u;  // L2(i-1)

    uint32_t af[2][4][4];
    if (G1) {
#pragma unroll
        for (int mt = 0; mt < 2; mt++)
#pragma unroll
            for (int ks = 0; ks < 4; ks++) {
                uint32_t addr = fR + (uint32_t)((half34 * 32 + mt * 16 + aRow) * LDR
                                                + ks * 16 + aCol) * 2u;
                LDSM4(af[mt][ks][0], af[mt][ks][1], af[mt][ks][2], af[mt][ks][3], addr);
            }
    }

#pragma unroll
    for (int p = 0; p < 4; p++) {
        if (G2) {
            // pack z tiles {2p, 2p+1} -> A k16-group, consume BEFORE rebuild
            uint32_t zA[2][4];
#pragma unroll
            for (int mt = 0; mt < 2; mt++) {
                zA[mt][0] = packh2(z[mt][2 * p][0],     z[mt][2 * p][1]);
                zA[mt][1] = packh2(z[mt][2 * p][2],     z[mt][2 * p][3]);
                zA[mt][2] = packh2(z[mt][2 * p + 1][0], z[mt][2 * p + 1][1]);
                zA[mt][3] = packh2(z[mt][2 * p + 1][2], z[mt][2 * p + 1][3]);
            }
            uint32_t lB[4][4];
#pragma unroll
            for (int q = 0; q < 4; q++) {
                uint32_t addr = fL + (uint32_t)((q * 16 + bRow) * LDR
                                                + p * 16 + bCol) * 2u;
                LDSM4(lB[q][0], lB[q][1], lB[q][2], lB[q][3], addr);
            }
#pragma unroll
            for (int q = 0; q < 4; q++)
#pragma unroll
                for (int mt = 0; mt < 2; mt++) {
                    MMA16(accY[mt][2 * q],     zA[mt][0], zA[mt][1], zA[mt][2], zA[mt][3],
                          lB[q][0], lB[q][1]);
                    MMA16(accY[mt][2 * q + 1], zA[mt][0], zA[mt][1], zA[mt][2], zA[mt][3],
                          lB[q][2], lB[q][3]);
                }
        }
        if (G1) {
            // rebuild z tiles {2p, 2p+1} in place: fresh write at ks=0
            uint32_t xb[4][4];
#pragma unroll
            for (int ks = 0; ks < 4; ks++) {
                uint32_t addr = sb + (uint32_t)(OFF_X +
                    (bb * 64 + p * 16 + bRow) * LDX + ks * 16 + bCol) * 2u;
                LDSM4(xb[ks][0], xb[ks][1], xb[ks][2], xb[ks][3], addr);
            }
#pragma unroll
            for (int mt = 0; mt < 2; mt++) {
                MMA16Z(z[mt][2 * p],     af[mt][0][0], af[mt][0][1], af[mt][0][2], af[mt][0][3],
                       xb[0][0], xb[0][1]);
                MMA16Z(z[mt][2 * p + 1], af[mt][0][0], af[mt][0][1], af[mt][0][2], af[mt][0][3],
                       xb[0][2], xb[0][3]);
            }
#pragma unroll
            for (int ks = 1; ks < 4; ks++)
#pragma unroll
                for (int mt = 0; mt < 2; mt++) {
                    MMA16(z[mt][2 * p],     af[mt][ks][0], af[mt][ks][1], af[mt][ks][2], af[mt][ks][3],
                          xb[ks][0], xb[ks][1]);
                    MMA16(z[mt][2 * p + 1], af[mt][ks][0], af[mt][ks][1], af[mt][ks][2], af[mt][ks][3],
                          xb[ks][2], xb[ks][3]);
                }
        }
    }
}

// ---------------- fused main kernel -----------------------------------------
__global__ void __launch_bounds__(256, 1)
tt_fused(const float* __restrict__ x, const float* __restrict__ bias,
         float* __restrict__ y) {
    extern __shared__ __half sm[];
    const uint32_t sb = smem_u32(sm);
    const int tid = threadIdx.x, wid = tid >> 5, lane = tid & 31;
    const int g = lane >> 2, t4 = lane & 3;
    const int b0 = blockIdx.x * 4;

    const int bb = wid & 3;           // warp's sample
    const int half34 = wid >> 2;      // warp's n34-half

    const int aRow = lane & 15,                      aCol = (lane >> 4) * 8;
    const int bRow = ((lane >> 4) * 8) + (lane & 7), bCol = ((lane >> 3) & 1) * 8;

    // ---- load X (4 samples x 4096 fp32) -> fp16 SMEM [(b,m12)][m34] --------
    {
        const float4* gx = reinterpret_cast<const float4*>(x + (size_t)b0 * 4096);
        __half* sX = sm + OFF_X;
#pragma unroll
        for (int j = 0; j < 16; j++) {
            int i = tid + j * 256;
            int row = i >> 4, c = i & 15;
            float4 v = gx[i];
            *reinterpret_cast<__half2*>(sX + row * LDX + c * 4)     = __floats2half2_rn(v.x, v.y);
            *reinterpret_cast<__half2*>(sX + row * LDX + c * 4 + 2) = __floats2half2_rn(v.z, v.w);
        }
    }
    prefetch_slot(sb, tid, 0);
    prefetch_slot(sb, tid, 1);
    prefetch_slot(sb, tid, 2);
    prefetch_slot(sb, tid, 3);
    CP_WAIT0();
    __syncthreads();           // X + slots 0..3 published

    float z[2][8][4];          // written fresh by MMA16Z in body 0
    float accY[2][8][4];
#pragma unroll
    for (int a = 0; a < 2; a++)
#pragma unroll
        for (int b = 0; b < 8; b++)
#pragma unroll
            for (int d = 0; d < 4; d++) accY[a][b][d] = 0.f;

    auto slot_addr = [&](int i) -> uint32_t {
        return sb + (uint32_t)(OFF_F + (i & (NSLOT - 1)) * FBUF) * 2u;
    };

    // body 0: GEMM1(0) only
    prefetch_slot(sb, tid, 4);
    body<false, true>(sb, slot_addr(0), z, accY, half34, bb, aRow, aCol, bRow, bCol);

#pragma unroll 1
    for (int i = 1; i < 16; i++) {
        if ((i & 3) == 0) { CP_WAIT0(); __syncthreads(); }   // publish window
        if (i <= 12) prefetch_slot(sb, tid, i + 4);
        body<true, true>(sb, slot_addr(i), z, accY, half34, bb, aRow, aCol, bRow, bCol);
    }

    CP_WAIT0();
    __syncthreads();
    // body 16: GEMM2(15) only (slot 16 -> phys 0, holds L2(15))
    body<true, false>(sb, slot_addr(16), z, accY, half34, bb, aRow, aCol, bRow, bCol);

    // ---- epilogue: y[b0+bb][n12*64 + n34] = Yt + bias -----------------------
    float* yb = y + (size_t)(b0 + bb) * 4096;
#pragma unroll
    for (int mt = 0; mt < 2; mt++) {
        const int n34r = half34 * 32 + mt * 16 + g;
#pragma unroll
        for (int n8 = 0; n8 < 8; n8++) {
            const int n12c = n8 * 8 + t4 * 2;
            const int e00 = n12c * 64 + n34r;
            const int e10 = e00 + 64;
            yb[e00]     = accY[mt][n8][0] + __ldg(bias + e00);
            yb[e10]     = accY[mt][n8][1] + __ldg(bias + e10);
            yb[e00 + 8] = accY[mt][n8][2] + __ldg(bias + e00 + 8);
            yb[e10 + 8] = accY[mt][n8][3] + __ldg(bias + e10 + 8);
        }
    }
}

// ---------------- launch -----------------------------------------------------
extern "C" void kernel_launch(void* const* d_in, const int* in_sizes, int n_in,
                              void* d_out, int out_size) {
    const float* x    = (const float*)d_in[0];
    const float* c0   = (const float*)d_in[1];
    const float* c1   = (const float*)d_in[2];
    const float* c2   = (const float*)d_in[3];
    const float* c3   = (const float*)d_in[4];
    const float* bias = (const float*)d_in[5];
    float* out = (float*)d_out;

    k_prep<<<512, 256>>>(c0, c1, c2, c3);

    cudaFuncSetAttribute(tt_fused, cudaFuncAttributeMaxDynamicSharedMemorySize, SMEM_BYTES);
    tt_fused<<<2048, 256, SMEM_BYTES>>>(x, bias, out);
}